// round 14
// baseline (speedup 1.0000x reference)
#include <cuda_runtime.h>
#include <cuda_bf16.h>
#include <cstdint>

#define T_STEPS 100

// ------------- device scratch (static; no allocations allowed) -------------
__device__ __align__(16) float2        g_basal2[T_STEPS * 256]; // {0.5*bm, 1.5*bm - bias}
__device__ __align__(16) float         g_q0[256];
__device__ __align__(16) __nv_bfloat16 g_W1T[256 * 256];        // [n][k] = Wapical[k][n]
__device__ __align__(16) __nv_bfloat16 g_W2T[256 * 256];        // [n][k] = Wca1ec5[k][n]

// ------------------------------ helpers ------------------------------------
__device__ __forceinline__ uint32_t smem_u32(const void* p) {
    uint32_t a;
    asm("{ .reg .u64 t; cvta.to.shared.u64 t, %1; cvt.u32.u64 %0, t; }" : "=r"(a) : "l"(p));
    return a;
}
__device__ __forceinline__ float fast_tanh(float x) {
    float y; asm("tanh.approx.f32 %0, %1;" : "=f"(y) : "f"(x)); return y;
}
__device__ __forceinline__ uint32_t bf2(float lo, float hi) {
    uint32_t r;
    asm("cvt.rn.bf16x2.f32 %0, %1, %2;" : "=r"(r) : "f"(hi), "f"(lo));
    return r;
}
#define CSYNC() do { \
    asm volatile("barrier.cluster.arrive.aligned;" ::: "memory"); \
    asm volatile("barrier.cluster.wait.aligned;" ::: "memory"); } while (0)

#define MBAR_INIT(addr, cnt) \
    asm volatile("mbarrier.init.shared.b64 [%0], %1;" :: "r"(addr), "r"((uint32_t)(cnt)) : "memory")

__device__ __forceinline__ void mbar_arrive_cnt(uint32_t a, uint32_t n) {
    asm volatile("mbarrier.arrive.shared.b64 _, [%0], %1;" :: "r"(a), "r"(n) : "memory");
}
__device__ __forceinline__ void mbar_arrive_remote(uint32_t a) {
    asm volatile("mbarrier.arrive.release.cluster.shared::cluster.b64 _, [%0];"
                 :: "r"(a) : "memory");
}
__device__ __forceinline__ void mbar_waitc(uint32_t mbar, uint32_t parity) {
    asm volatile(
        "{\n\t.reg .pred P;\n\t"
        "WL%=:\n\t"
        "mbarrier.try_wait.parity.acquire.cluster.shared::cta.b64 P, [%0], %1, 0x989680;\n\t"
        "@P bra.uni WD%=;\n\t"
        "bra.uni WL%=;\n\t"
        "WD%=:\n\t}"
        :: "r"(mbar), "r"(parity) : "memory");
}

#define LDSM4(R, addr) \
    asm volatile("ldmatrix.sync.aligned.m8n8.x4.shared.b16 {%0,%1,%2,%3}, [%4];" \
        : "=r"((R)[0]), "=r"((R)[1]), "=r"((R)[2]), "=r"((R)[3]) : "r"(addr))

#define MMA16816(D, A0, A1, A2, A3, B0, B1) \
    asm volatile("mma.sync.aligned.m16n8k16.row.col.f32.bf16.bf16.f32 " \
        "{%0,%1,%2,%3}, {%4,%5,%6,%7}, {%8,%9}, {%0,%1,%2,%3};" \
        : "+f"((D)[0]), "+f"((D)[1]), "+f"((D)[2]), "+f"((D)[3]) \
        : "r"(A0), "r"(A1), "r"(A2), "r"(A3), "r"(B0), "r"(B1))

// SW128 blocked layout. 32KB regions: [128 rows x 128 cols], 2 x 64-col blocks;
// 64KB B tiles: [128 rows x 256 cols], 4 blocks. col is region-relative.
__device__ __forceinline__ uint32_t tile_off(int row, int col) {
    uint32_t b = (uint32_t)((((row >> 3) + (col >> 6) * 16) << 10) +
                            ((row & 7) << 7) + ((col & 63) << 1));
    return b ^ ((b >> 3) & 0x70);
}

// ------------------------------ prep kernels -------------------------------
__global__ void prep_basal(const float* __restrict__ Wb, const float* __restrict__ bias) {
    __shared__ float ca3[256];
    int t = blockIdx.x, c = threadIdx.x;
    float x = (float)(t + 1);
    float d = x - (float)c * (100.0f / 255.0f);
    ca3[c] = expf(-d * d * (1.0f / 50.0f));
    __syncthreads();
    float s = 0.f;
    for (int j = 0; j < 256; j++) s = fmaf(ca3[j], Wb[j * 256 + c], s);
    g_basal2[t * 256 + c] = make_float2(0.5f * s, fmaf(1.5f, s, -bias[c]));
}

__global__ void prep_w(const float* __restrict__ W1, const float* __restrict__ W2) {
    int n = blockIdx.x & 255, k = threadIdx.x;
    if (blockIdx.x < 256) g_W1T[n * 256 + k] = __float2bfloat16(W1[k * 256 + n]);
    else                  g_W2T[n * 256 + k] = __float2bfloat16(W2[k * 256 + n]);
}

__global__ void prep_q0(const float* __restrict__ W2) {
    __shared__ float ca10[256];
    int e = threadIdx.x;
    ca10[e] = fmaxf(g_basal2[e].y, 0.f);
    __syncthreads();
    float s = 0.f;
    for (int c = 0; c < 256; c++) s = fmaf(ca10[c], W2[c * 256 + e], s);
    g_q0[e] = s;
}

// ------------------------------- main kernel -------------------------------
// SMEM: mbars @0; Aloc @1024 (32KB, own cols: ca1/e3 alternate);
// peerE3 @33792 (32KB, peer remote-stores); peerCA1 @66560 (32KB, peer stores);
// B1 @99328 (64KB); B2 @164864 (64KB). Total 230400 <= 227KB max dynamic.
#define SM_MB    0
#define SM_ALOC  1024
#define SM_PE3   33792
#define SM_PCA   66560
#define SM_B1    99328
#define SM_B2    164864
#define SM_TOTAL 230400
#define NTHR     512

// one 64-col K block (4 kt): warp tile m32 x n32; A from a 32KB region
// (region-relative block kb in {0,1}), B cols at global K = bcol0 + kb*64 + ...
__device__ __forceinline__ void gemm_blk(uint32_t a_region, uint32_t b_base, int bcol0,
                                         float* acc, int arow, int aoff,
                                         int brow, int boff, int kb) {
#pragma unroll
    for (int q = 0; q < 4; q++) {
        const int ac = kb * 64 + q * 16;
        const int bc = bcol0 + kb * 64 + q * 16;
        uint32_t a0[4], a1[4], b[2][4];
        LDSM4(a0, a_region + tile_off(arow, ac + aoff));
        LDSM4(a1, a_region + tile_off(arow + 16, ac + aoff));
        LDSM4(b[0], b_base + tile_off(brow, bc + boff));
        LDSM4(b[1], b_base + tile_off(brow + 16, bc + boff));
#pragma unroll
        for (int nt = 0; nt < 4; nt++) {
            MMA16816(&acc[nt * 4], a0[0], a0[1], a0[2], a0[3],
                     b[nt >> 1][(nt & 1) * 2], b[nt >> 1][(nt & 1) * 2 + 1]);
            MMA16816(&acc[16 + nt * 4], a1[0], a1[1], a1[2], a1[3],
                     b[nt >> 1][(nt & 1) * 2], b[nt >> 1][(nt & 1) * 2 + 1]);
        }
    }
}

__global__ void __launch_bounds__(NTHR, 1) __cluster_dims__(2, 1, 1)
rnn_main(const float* __restrict__ cue, const float* __restrict__ ec5i,
         const float* __restrict__ Waction, float* __restrict__ out) {
    extern __shared__ char smem[];
    const uint32_t sbase = smem_u32(smem);
    const int tid = threadIdx.x, lane = tid & 31, wid = tid >> 5;
    const int mq = wid >> 2;                 // M quarter 0..3 (32 rows)
    const int nq = wid & 3;                  // N quarter 0..3 (32 cols)
    const int group = lane >> 2, tid4 = lane & 3;
    const int rank = blockIdx.x & 1;
    const int prk = rank ^ 1;
    const int gbase = (blockIdx.x >> 1) * 128;
    const int mrow0 = 32 * mq;
    const int colq = rank * 128 + 32 * nq;   // GLOBAL col base (gmem/basal indexing)
    const int crel = 32 * nq;                // region-relative col base
    const int arow = mrow0 + (lane & 15), aoff = (lane >> 4) * 8;
    const int brow = 32 * nq + ((lane >> 4) << 3) + (lane & 7);
    const int boff = ((lane >> 3) & 1) << 3;
    const int bl = rank * 128, bp = prk * 128;   // B col offsets: local/peer K half
    const int gbar = 1 + mq;

    const uint32_t aloc = sbase + SM_ALOC;
    const uint32_t pe3  = sbase + SM_PE3;
    const uint32_t pca  = sbase + SM_PCA;
    const uint32_t b1base = sbase + SM_B1, b2base = sbase + SM_B2;
    const uint32_t F1 = sbase + SM_MB, F2 = F1 + 8;
    uint32_t rPE3, rPCA, pF1, pF2;   // peer-CTA addresses
    asm("mapa.shared::cluster.u32 %0, %1, %2;" : "=r"(rPE3) : "r"(pe3), "r"(prk));
    asm("mapa.shared::cluster.u32 %0, %1, %2;" : "=r"(rPCA) : "r"(pca), "r"(prk));
    asm("mapa.shared::cluster.u32 %0, %1, %2;" : "=r"(pF1)  : "r"(F1),  "r"(prk));
    asm("mapa.shared::cluster.u32 %0, %1, %2;" : "=r"(pF2)  : "r"(F2),  "r"(prk));

    if (tid == 0) { MBAR_INIT(F1, 16); MBAR_INIT(F2, 16); }

    // ---- init: Aloc = cue own cols, peerE3 = cue peer cols (local writes) ----
    {
        const float4* src = (const float4*)(cue + (size_t)gbase * 256);
        for (int idx = tid; idx < 8192; idx += NTHR) {
            int r = idx >> 6, c4 = (idx & 63) * 4;       // global col c4..c4+3
            float4 v = src[idx];
            uint32_t p0 = bf2(v.x, v.y), p1 = bf2(v.z, v.w);
            uint32_t reg = ((c4 >> 7) == rank) ? aloc : pe3;
            asm volatile("st.shared.v2.b32 [%0], {%1,%2};"
                         :: "r"(reg + tile_off(r, c4 & 127)), "r"(p0), "r"(p1) : "memory");
        }
    }
    // ---- resident weights (this CTA's 128-row N-half of W1T/W2T) ----
    {
        const uint4* w1 = (const uint4*)(g_W1T + (size_t)rank * 128 * 256);
        const uint4* w2 = (const uint4*)(g_W2T + (size_t)rank * 128 * 256);
        for (int idx = tid; idx < 4096; idx += NTHR) {
            int r = idx >> 5, c8 = (idx & 31) * 8;
            *(uint4*)(smem + SM_B1 + tile_off(r, c8)) = w1[idx];
            *(uint4*)(smem + SM_B2 + tile_off(r, c8)) = w2[idx];
        }
    }

    // ---- per-thread state: e5 = clip(ec5i + q0) f32; e3p = cue packed bf16 ----
    float e5[32], d[32];
    uint32_t e3p[16];
#pragma unroll
    for (int mt = 0; mt < 2; mt++)
#pragma unroll
        for (int half = 0; half < 2; half++) {
            int row = gbase + mrow0 + 16 * mt + group + 8 * half;
#pragma unroll
            for (int nt = 0; nt < 4; nt++) {
                int cg = colq + 8 * nt + 2 * tid4;
                int j = mt * 16 + nt * 4 + half * 2;
                float2 v5 = *(const float2*)(ec5i + (size_t)row * 256 + cg);
                float2 q  = *(const float2*)(g_q0 + cg);
                e5[j]     = fminf(fmaxf(v5.x + q.x, 0.f), 1.f);
                e5[j + 1] = fminf(fmaxf(v5.y + q.y, 0.f), 1.f);
                float2 v3 = *(const float2*)(cue + (size_t)row * 256 + cg);
                e3p[mt * 8 + nt * 2 + half] = bf2(v3.x, v3.y);
            }
        }
    __syncthreads();
    if (tid == 0) mbar_arrive_cnt(F2, 16);   // F2 phase0: peerE3 pre-filled with cue
    CSYNC();  // mbars + tiles visible cluster-wide

    for (int i = 1; i < T_STEPS; i++) {
        const uint32_t par = (uint32_t)(i - 1) & 1u;

        // ---- GEMM1: S = ec3 @ W1 (Aloc halves, wait F2, peerE3 halves) ----
#pragma unroll
        for (int j = 0; j < 32; j++) d[j] = 0.f;
        gemm_blk(aloc, b1base, bl, d, arow, aoff, brow, boff, 0);
        gemm_blk(aloc, b1base, bl, d, arow, aoff, brow, boff, 1);
        mbar_waitc(F2, par);
        gemm_blk(pe3, b1base, bp, d, arow, aoff, brow, boff, 0);
        gemm_blk(pe3, b1base, bp, d, arow, aoff, brow, boff, 1);

        if (i < T_STEPS - 1) {
            // ---- epilogue1: ca1 = relu(fma(0.5bm, tanh(S/2), 1.5bm-bias)) ----
#pragma unroll
            for (int nt = 0; nt < 4; nt++) {
                float4 bb = *(const float4*)(&g_basal2[i * 256 + colq + 8 * nt + 2 * tid4]);
#pragma unroll
                for (int mt = 0; mt < 2; mt++)
#pragma unroll
                    for (int half = 0; half < 2; half++) {
                        int j = mt * 16 + nt * 4 + half * 2;
                        d[j]     = fmaxf(fmaf(bb.x, fast_tanh(0.5f * d[j]),     bb.y), 0.f);
                        d[j + 1] = fmaxf(fmaf(bb.z, fast_tanh(0.5f * d[j + 1]), bb.w), 0.f);
                    }
            }
            asm volatile("bar.sync %0, 128;" :: "r"(gbar) : "memory");  // WAR (group)
            // store ca1: local Aloc + remote peer PCA (same region offset)
#pragma unroll
            for (int mt = 0; mt < 2; mt++)
#pragma unroll
                for (int half = 0; half < 2; half++) {
                    int row = mrow0 + 16 * mt + group + 8 * half;
#pragma unroll
                    for (int nt = 0; nt < 4; nt++) {
                        int j = mt * 16 + nt * 4 + half * 2;
                        uint32_t p = bf2(d[j], d[j + 1]);
                        uint32_t off = tile_off(row, crel + 8 * nt + 2 * tid4);
                        asm volatile("st.shared.b32 [%0], %1;"
                            :: "r"(aloc + off), "r"(p) : "memory");
                        asm volatile("st.shared::cluster.b32 [%0], %1;"
                            :: "r"(rPCA + off), "r"(p) : "memory");
                    }
                }
            asm volatile("bar.sync %0, 128;" :: "r"(gbar) : "memory");  // RAW (group)
            __syncwarp();
            if (lane == 0) mbar_arrive_remote(pF1);   // 16 arrivals complete peer F1

            // ---- GEMM2: e5 += ca1 @ W2 ----
            gemm_blk(aloc, b2base, bl, e5, arow, aoff, brow, boff, 0);
            gemm_blk(aloc, b2base, bl, e5, arow, aoff, brow, boff, 1);
            mbar_waitc(F1, par);
            gemm_blk(pca, b2base, bp, e5, arow, aoff, brow, boff, 0);
            gemm_blk(pca, b2base, bp, e5, arow, aoff, brow, boff, 1);

            // ---- epilogue2: clip e5; e3 *= e5 (f32 math, packed storage) ----
#pragma unroll
            for (int mt = 0; mt < 2; mt++)
#pragma unroll
                for (int half = 0; half < 2; half++)
#pragma unroll
                    for (int nt = 0; nt < 4; nt++) {
                        int j = mt * 16 + nt * 4 + half * 2;
                        int j2 = mt * 8 + nt * 2 + half;
                        float v0 = fminf(fmaxf(e5[j], 0.f), 1.f);
                        float v1 = fminf(fmaxf(e5[j + 1], 0.f), 1.f);
                        e5[j] = v0; e5[j + 1] = v1;
                        uint32_t ep = e3p[j2];
                        float t0 = __bfloat162float(*(__nv_bfloat16*)&ep);
                        uint32_t hi = ep >> 16;
                        float t1 = __bfloat162float(*(__nv_bfloat16*)&hi);
                        e3p[j2] = bf2(t0 * v0, t1 * v1);
                    }
            asm volatile("bar.sync %0, 128;" :: "r"(gbar) : "memory");  // WAR (group)
#pragma unroll
            for (int mt = 0; mt < 2; mt++)
#pragma unroll
                for (int half = 0; half < 2; half++) {
                    int row = mrow0 + 16 * mt + group + 8 * half;
#pragma unroll
                    for (int nt = 0; nt < 4; nt++) {
                        uint32_t p = e3p[mt * 8 + nt * 2 + half];
                        uint32_t off = tile_off(row, crel + 8 * nt + 2 * tid4);
                        asm volatile("st.shared.b32 [%0], %1;"
                            :: "r"(aloc + off), "r"(p) : "memory");
                        asm volatile("st.shared::cluster.b32 [%0], %1;"
                            :: "r"(rPE3 + off), "r"(p) : "memory");
                    }
                }
            asm volatile("bar.sync %0, 128;" :: "r"(gbar) : "memory");  // RAW (group)
            __syncwarp();
            if (lane == 0) mbar_arrive_remote(pF2);   // 16 arrivals complete peer F2
        } else {
            // ---- final step: ca1_99 -> out = ca1 @ Waction ----
#pragma unroll
            for (int nt = 0; nt < 4; nt++) {
                float4 bb = *(const float4*)(&g_basal2[i * 256 + colq + 8 * nt + 2 * tid4]);
#pragma unroll
                for (int mt = 0; mt < 2; mt++)
#pragma unroll
                    for (int half = 0; half < 2; half++) {
                        int j = mt * 16 + nt * 4 + half * 2;
                        d[j]     = fmaxf(fmaf(bb.x, fast_tanh(0.5f * d[j]),     bb.y), 0.f);
                        d[j + 1] = fmaxf(fmaf(bb.z, fast_tanh(0.5f * d[j + 1]), bb.w), 0.f);
                    }
            }
            float* red1 = (float*)(smem + SM_B2);   // B2 dead: [128][2][16]
            float* red2 = (float*)(smem + SM_PCA);  // peerCA1 dead in final step
            __syncthreads();                        // all warps past B2/PCA reads
            int ct = nq * 4 + tid4;
#pragma unroll
            for (int mt = 0; mt < 2; mt++)
#pragma unroll
                for (int half = 0; half < 2; half++) {
                    float p0 = 0.f, p1 = 0.f;
#pragma unroll
                    for (int nt = 0; nt < 4; nt++)
#pragma unroll
                        for (int c = 0; c < 2; c++) {
                            int cg = colq + 8 * nt + 2 * tid4 + c;
                            float v = d[mt * 16 + nt * 4 + half * 2 + c];
                            p0 = fmaf(v, Waction[cg * 2 + 0], p0);
                            p1 = fmaf(v, Waction[cg * 2 + 1], p1);
                        }
                    int row = mrow0 + 16 * mt + group + 8 * half;
                    red1[(row * 2 + 0) * 16 + ct] = p0;
                    red1[(row * 2 + 1) * 16 + ct] = p1;
                }
            __syncthreads();
            float s = 0.f;
            if (tid < 256) {
                int row = tid >> 1, a = tid & 1;
#pragma unroll
                for (int k = 0; k < 16; k++) s += red1[(row * 2 + a) * 16 + k];
                if (rank == 1) {
                    uint32_t r2;
                    asm("mapa.shared::cluster.u32 %0, %1, %2;"
                        : "=r"(r2) : "r"((uint32_t)(sbase + SM_PCA + (row * 2 + a) * 4)), "r"(0));
                    asm volatile("st.shared::cluster.b32 [%0], %1;" :: "r"(r2), "f"(s) : "memory");
                }
            }
            CSYNC();
            if (tid < 256 && rank == 0) {
                int row = tid >> 1, a = tid & 1;
                out[(size_t)(gbase + row) * 2 + a] = s + red2[row * 2 + a];
            }
            CSYNC();  // keep cluster alive until all remote traffic done
        }
    }
}

// ------------------------------ launch glue --------------------------------
extern "C" void kernel_launch(void* const* d_in, const int* in_sizes, int n_in,
                              void* d_out, int out_size) {
    const float* cue  = (const float*)d_in[0];
    const float* ec5i = (const float*)d_in[1];
    const float* W1   = (const float*)d_in[2];  // Wapical
    const float* Wb   = (const float*)d_in[3];  // Wbasal
    const float* W2   = (const float*)d_in[4];  // Wca1ec5
    const float* Wa   = (const float*)d_in[5];  // Waction
    const float* bias = (const float*)d_in[6];  // ca1bias
    float* out = (float*)d_out;

    prep_basal<<<100, 256>>>(Wb, bias);
    prep_w<<<512, 256>>>(W1, W2);
    prep_q0<<<1, 256>>>(W2);

    cudaFuncSetAttribute(rnn_main, cudaFuncAttributeMaxDynamicSharedMemorySize, SM_TOTAL);
    rnn_main<<<512, NTHR, SM_TOTAL>>>(cue, ec5i, Wa, out);
}

// round 15
// speedup vs baseline: 1.2032x; 1.2032x over previous
#include <cuda_runtime.h>
#include <cuda_bf16.h>
#include <cstdint>

#define T_STEPS 100

// ------------- device scratch (static; no allocations allowed) -------------
__device__ __align__(16) float2        g_basal2[T_STEPS * 256]; // {0.5*bm, 1.5*bm - bias}
__device__ __align__(16) float         g_q0[256];
__device__ __align__(16) __nv_bfloat16 g_W1T[256 * 256];        // [n][k] = Wapical[k][n]
__device__ __align__(16) __nv_bfloat16 g_W2T[256 * 256];        // [n][k] = Wca1ec5[k][n]

// ------------------------------ helpers ------------------------------------
__device__ __forceinline__ uint32_t smem_u32(const void* p) {
    uint32_t a;
    asm("{ .reg .u64 t; cvta.to.shared.u64 t, %1; cvt.u32.u64 %0, t; }" : "=r"(a) : "l"(p));
    return a;
}
__device__ __forceinline__ float fast_tanh(float x) {
    float y; asm("tanh.approx.f32 %0, %1;" : "=f"(y) : "f"(x)); return y;
}
__device__ __forceinline__ uint32_t bf2(float lo, float hi) {
    uint32_t r;
    asm("cvt.rn.bf16x2.f32 %0, %1, %2;" : "=r"(r) : "f"(hi), "f"(lo));
    return r;
}
#define CSYNC() do { \
    asm volatile("barrier.cluster.arrive.aligned;" ::: "memory"); \
    asm volatile("barrier.cluster.wait.aligned;" ::: "memory"); } while (0)

#define MBAR_INIT(addr, cnt) \
    asm volatile("mbarrier.init.shared.b64 [%0], %1;" :: "r"(addr), "r"((uint32_t)(cnt)) : "memory")

__device__ __forceinline__ void mbar_arrive_local(uint32_t a) {
    asm volatile("mbarrier.arrive.shared.b64 _, [%0];" :: "r"(a) : "memory");
}
__device__ __forceinline__ void mbar_arrive_remote(uint32_t a) {
    asm volatile("mbarrier.arrive.release.cluster.shared::cluster.b64 _, [%0];"
                 :: "r"(a) : "memory");
}
__device__ __forceinline__ void mbar_arm_tx(uint32_t a, uint32_t bytes) {
    asm volatile("mbarrier.arrive.expect_tx.shared.b64 _, [%0], %1;"
                 :: "r"(a), "r"(bytes) : "memory");
}
__device__ __forceinline__ void mbar_waitc(uint32_t mbar, uint32_t parity) {
    asm volatile(
        "{\n\t.reg .pred P;\n\t"
        "WL%=:\n\t"
        "mbarrier.try_wait.parity.acquire.cluster.shared::cta.b64 P, [%0], %1, 0x989680;\n\t"
        "@P bra.uni WD%=;\n\t"
        "bra.uni WL%=;\n\t"
        "WD%=:\n\t}"
        :: "r"(mbar), "r"(parity) : "memory");
}
// DSMEM DMA: local smem -> peer smem, completes on peer's mbarrier (tx bytes)
__device__ __forceinline__ void bulk_to_peer(uint32_t dst, uint32_t src, uint32_t bytes,
                                             uint32_t peer_mbar) {
    asm volatile(
        "cp.async.bulk.shared::cluster.shared::cta.mbarrier::complete_tx::bytes "
        "[%0], [%1], %2, [%3];"
        :: "r"(dst), "r"(src), "r"(bytes), "r"(peer_mbar) : "memory");
}
#define FENCE_ASYNC() asm volatile("fence.proxy.async.shared::cta;" ::: "memory")

#define LDSM4(R, addr) \
    asm volatile("ldmatrix.sync.aligned.m8n8.x4.shared.b16 {%0,%1,%2,%3}, [%4];" \
        : "=r"((R)[0]), "=r"((R)[1]), "=r"((R)[2]), "=r"((R)[3]) : "r"(addr))

#define MMA16816(D, A0, A1, A2, A3, B0, B1) \
    asm volatile("mma.sync.aligned.m16n8k16.row.col.f32.bf16.bf16.f32 " \
        "{%0,%1,%2,%3}, {%4,%5,%6,%7}, {%8,%9}, {%0,%1,%2,%3};" \
        : "+f"((D)[0]), "+f"((D)[1]), "+f"((D)[2]), "+f"((D)[3]) \
        : "r"(A0), "r"(A1), "r"(A2), "r"(A3), "r"(B0), "r"(B1))

// SW128 blocked layout. 32KB regions: [128 rows x 128 cols], 2 x 64-col blocks
// (each block = contiguous 16KB); 64KB B tiles: 4 blocks. col region-relative.
__device__ __forceinline__ uint32_t tile_off(int row, int col) {
    uint32_t b = (uint32_t)((((row >> 3) + (col >> 6) * 16) << 10) +
                            ((row & 7) << 7) + ((col & 63) << 1));
    return b ^ ((b >> 3) & 0x70);
}

// ------------------------------ prep kernels -------------------------------
__global__ void prep_basal(const float* __restrict__ Wb, const float* __restrict__ bias) {
    __shared__ float ca3[256];
    int t = blockIdx.x, c = threadIdx.x;
    float x = (float)(t + 1);
    float d = x - (float)c * (100.0f / 255.0f);
    ca3[c] = expf(-d * d * (1.0f / 50.0f));
    __syncthreads();
    float s = 0.f;
    for (int j = 0; j < 256; j++) s = fmaf(ca3[j], Wb[j * 256 + c], s);
    g_basal2[t * 256 + c] = make_float2(0.5f * s, fmaf(1.5f, s, -bias[c]));
}

__global__ void prep_w(const float* __restrict__ W1, const float* __restrict__ W2) {
    int n = blockIdx.x & 255, k = threadIdx.x;
    if (blockIdx.x < 256) g_W1T[n * 256 + k] = __float2bfloat16(W1[k * 256 + n]);
    else                  g_W2T[n * 256 + k] = __float2bfloat16(W2[k * 256 + n]);
}

__global__ void prep_q0(const float* __restrict__ W2) {
    __shared__ float ca10[256];
    int e = threadIdx.x;
    ca10[e] = fmaxf(g_basal2[e].y, 0.f);
    __syncthreads();
    float s = 0.f;
    for (int c = 0; c < 256; c++) s = fmaf(ca10[c], W2[c * 256 + e], s);
    g_q0[e] = s;
}

// ------------------------------- main kernel -------------------------------
// SMEM: mbars @0; Aloc @1024 (32KB); peerE3 @33792 (32KB, DMA dest);
// peerCA1 @66560 (32KB, DMA dest); B1 @99328 (64KB); B2 @164864 (64KB).
#define SM_MB    0
#define SM_ALOC  1024
#define SM_PE3   33792
#define SM_PCA   66560
#define SM_B1    99328
#define SM_B2    164864
#define SM_TOTAL 230400
#define NTHR     512

// one 64-col K block (4 kt): warp tile m32 x n32; A from a 32KB region
__device__ __forceinline__ void gemm_blk(uint32_t a_region, uint32_t b_base, int bcol0,
                                         float* acc, int arow, int aoff,
                                         int brow, int boff, int kb) {
#pragma unroll
    for (int q = 0; q < 4; q++) {
        const int ac = kb * 64 + q * 16;
        const int bc = bcol0 + kb * 64 + q * 16;
        uint32_t a0[4], a1[4], b[2][4];
        LDSM4(a0, a_region + tile_off(arow, ac + aoff));
        LDSM4(a1, a_region + tile_off(arow + 16, ac + aoff));
        LDSM4(b[0], b_base + tile_off(brow, bc + boff));
        LDSM4(b[1], b_base + tile_off(brow + 16, bc + boff));
#pragma unroll
        for (int nt = 0; nt < 4; nt++) {
            MMA16816(&acc[nt * 4], a0[0], a0[1], a0[2], a0[3],
                     b[nt >> 1][(nt & 1) * 2], b[nt >> 1][(nt & 1) * 2 + 1]);
            MMA16816(&acc[16 + nt * 4], a1[0], a1[1], a1[2], a1[3],
                     b[nt >> 1][(nt & 1) * 2], b[nt >> 1][(nt & 1) * 2 + 1]);
        }
    }
}

__global__ void __launch_bounds__(NTHR, 1) __cluster_dims__(2, 1, 1)
rnn_main(const float* __restrict__ cue, const float* __restrict__ ec5i,
         const float* __restrict__ Waction, float* __restrict__ out) {
    extern __shared__ char smem[];
    const uint32_t sbase = smem_u32(smem);
    const int tid = threadIdx.x, lane = tid & 31, wid = tid >> 5;
    const int mq = wid >> 2;                 // M quarter 0..3 (32 rows)
    const int nq = wid & 3;                  // N quarter 0..3 (32 cols)
    const int group = lane >> 2, tid4 = lane & 3;
    const int rank = blockIdx.x & 1;
    const int prk = rank ^ 1;
    const int gbase = (blockIdx.x >> 1) * 128;
    const int mrow0 = 32 * mq;
    const int colq = rank * 128 + 32 * nq;   // GLOBAL col base
    const int crel = 32 * nq;                // region-relative col base
    const int arow = mrow0 + (lane & 15), aoff = (lane >> 4) * 8;
    const int brow = 32 * nq + ((lane >> 4) << 3) + (lane & 7);
    const int boff = ((lane >> 3) & 1) << 3;
    const int bl = rank * 128, bp = prk * 128;
    const int gbar = 1 + mq;
    const int myblk = nq >> 1;               // which 16KB half this warp stores

    const uint32_t aloc = sbase + SM_ALOC;
    const uint32_t pe3  = sbase + SM_PE3;
    const uint32_t pca  = sbase + SM_PCA;
    const uint32_t b1base = sbase + SM_B1, b2base = sbase + SM_B2;
    const uint32_t F1a = sbase + SM_MB,      F1b = F1a + 8;
    const uint32_t F2a = F1a + 16,           F2b = F1a + 24;
    const uint32_t aE3 = F1a + 32,           aC1 = F1a + 40;
    const uint32_t mSD0 = F1a + 48,          mSD1 = F1a + 56;
    const uint32_t mSDme = (myblk == 0) ? mSD0 : mSD1;
    uint32_t pPE3, pPCA, pF1a, pF1b, pF2a, pF2b, paE3, paC1;
    asm("mapa.shared::cluster.u32 %0, %1, %2;" : "=r"(pPE3) : "r"(pe3), "r"(prk));
    asm("mapa.shared::cluster.u32 %0, %1, %2;" : "=r"(pPCA) : "r"(pca), "r"(prk));
    asm("mapa.shared::cluster.u32 %0, %1, %2;" : "=r"(pF1a) : "r"(F1a), "r"(prk));
    asm("mapa.shared::cluster.u32 %0, %1, %2;" : "=r"(pF1b) : "r"(F1b), "r"(prk));
    asm("mapa.shared::cluster.u32 %0, %1, %2;" : "=r"(pF2a) : "r"(F2a), "r"(prk));
    asm("mapa.shared::cluster.u32 %0, %1, %2;" : "=r"(pF2b) : "r"(F2b), "r"(prk));
    asm("mapa.shared::cluster.u32 %0, %1, %2;" : "=r"(paE3) : "r"(aE3), "r"(prk));
    asm("mapa.shared::cluster.u32 %0, %1, %2;" : "=r"(paC1) : "r"(aC1), "r"(prk));

    if (tid == 0) {
        MBAR_INIT(F1a, 1); MBAR_INIT(F1b, 1);
        MBAR_INIT(F2a, 1); MBAR_INIT(F2b, 1);
        MBAR_INIT(aE3, 1); MBAR_INIT(aC1, 1);
        MBAR_INIT(mSD0, 8); MBAR_INIT(mSD1, 8);
    }

    // ---- init: Aloc = cue own cols, peerE3 = cue peer cols (local writes) ----
    {
        const float4* src = (const float4*)(cue + (size_t)gbase * 256);
        for (int idx = tid; idx < 8192; idx += NTHR) {
            int r = idx >> 6, c4 = (idx & 63) * 4;
            float4 v = src[idx];
            uint32_t p0 = bf2(v.x, v.y), p1 = bf2(v.z, v.w);
            uint32_t reg = ((c4 >> 7) == rank) ? aloc : pe3;
            asm volatile("st.shared.v2.b32 [%0], {%1,%2};"
                         :: "r"(reg + tile_off(r, c4 & 127)), "r"(p0), "r"(p1) : "memory");
        }
    }
    // ---- resident weights (this CTA's 128-row N-half of W1T/W2T) ----
    {
        const uint4* w1 = (const uint4*)(g_W1T + (size_t)rank * 128 * 256);
        const uint4* w2 = (const uint4*)(g_W2T + (size_t)rank * 128 * 256);
        for (int idx = tid; idx < 4096; idx += NTHR) {
            int r = idx >> 5, c8 = (idx & 31) * 8;
            *(uint4*)(smem + SM_B1 + tile_off(r, c8)) = w1[idx];
            *(uint4*)(smem + SM_B2 + tile_off(r, c8)) = w2[idx];
        }
    }

    // ---- per-thread state: e5 = clip(ec5i + q0) f32; e3p = cue packed bf16 ----
    float e5[32], d[32];
    uint32_t e3p[16];
#pragma unroll
    for (int mt = 0; mt < 2; mt++)
#pragma unroll
        for (int half = 0; half < 2; half++) {
            int row = gbase + mrow0 + 16 * mt + group + 8 * half;
#pragma unroll
            for (int nt = 0; nt < 4; nt++) {
                int cg = colq + 8 * nt + 2 * tid4;
                int j = mt * 16 + nt * 4 + half * 2;
                float2 v5 = *(const float2*)(ec5i + (size_t)row * 256 + cg);
                float2 q  = *(const float2*)(g_q0 + cg);
                e5[j]     = fminf(fmaxf(v5.x + q.x, 0.f), 1.f);
                e5[j + 1] = fminf(fmaxf(v5.y + q.y, 0.f), 1.f);
                float2 v3 = *(const float2*)(cue + (size_t)row * 256 + cg);
                e3p[mt * 8 + nt * 2 + half] = bf2(v3.x, v3.y);
            }
        }
    __syncthreads();
    if (tid == 0) {
        mbar_arrive_local(F2a); mbar_arrive_local(F2b);  // phase0: peerE3 prefilled
        mbar_arm_tx(F1a, 16384); mbar_arm_tx(F1b, 16384);
    }
    CSYNC();  // mbars + tiles + arms visible cluster-wide

    uint32_t sph0 = 0, sph1 = 0;  // mSD parities (tid0)

    for (int i = 1; i < T_STEPS; i++) {
        const uint32_t par = (uint32_t)(i - 1) & 1u;

        // ---- GEMM1: S = ec3 @ W1 (Aloc halves, then peerE3 halves, split waits) ----
#pragma unroll
        for (int j = 0; j < 32; j++) d[j] = 0.f;
        gemm_blk(aloc, b1base, bl, d, arow, aoff, brow, boff, 0);
        gemm_blk(aloc, b1base, bl, d, arow, aoff, brow, boff, 1);
        mbar_waitc(F2a, par);
        if (tid == 0) mbar_arm_tx(F2a, 16384);
        gemm_blk(pe3, b1base, bp, d, arow, aoff, brow, boff, 0);
        mbar_waitc(F2b, par);
        if (tid == 0) { mbar_arm_tx(F2b, 16384); mbar_arrive_remote(paE3); }
        gemm_blk(pe3, b1base, bp, d, arow, aoff, brow, boff, 1);

        if (i < T_STEPS - 1) {
            // ---- epilogue1: ca1 = relu(fma(0.5bm, tanh(S/2), 1.5bm-bias)) ----
#pragma unroll
            for (int nt = 0; nt < 4; nt++) {
                float4 bb = *(const float4*)(&g_basal2[i * 256 + colq + 8 * nt + 2 * tid4]);
#pragma unroll
                for (int mt = 0; mt < 2; mt++)
#pragma unroll
                    for (int half = 0; half < 2; half++) {
                        int j = mt * 16 + nt * 4 + half * 2;
                        d[j]     = fmaxf(fmaf(bb.x, fast_tanh(0.5f * d[j]),     bb.y), 0.f);
                        d[j + 1] = fmaxf(fmaf(bb.z, fast_tanh(0.5f * d[j + 1]), bb.w), 0.f);
                    }
            }
            mbar_waitc(aE3, par);   // prev e3-DMA fully delivered -> Aloc source free
            asm volatile("bar.sync %0, 128;" :: "r"(gbar) : "memory");  // WAR (group)
#pragma unroll
            for (int mt = 0; mt < 2; mt++)
#pragma unroll
                for (int half = 0; half < 2; half++) {
                    int row = mrow0 + 16 * mt + group + 8 * half;
#pragma unroll
                    for (int nt = 0; nt < 4; nt++) {
                        int j = mt * 16 + nt * 4 + half * 2;
                        uint32_t p = bf2(d[j], d[j + 1]);
                        asm volatile("st.shared.b32 [%0], %1;"
                            :: "r"(aloc + tile_off(row, crel + 8 * nt + 2 * tid4)), "r"(p)
                            : "memory");
                    }
                }
            asm volatile("bar.sync %0, 128;" :: "r"(gbar) : "memory");  // RAW (group)
            __syncwarp();
            if (lane == 0) mbar_arrive_local(mSDme);   // per-block store-done
            if (tid == 0) {
                mbar_waitc(mSD0, sph0); sph0 ^= 1;
                FENCE_ASYNC();
                bulk_to_peer(pPCA, aloc, 16384, pF1a);          // ship block 0
                mbar_waitc(mSD1, sph1); sph1 ^= 1;
                bulk_to_peer(pPCA + 16384, aloc + 16384, 16384, pF1b);  // block 1
            }

            // ---- GEMM2: e5 += ca1 @ W2 ----
            gemm_blk(aloc, b2base, bl, e5, arow, aoff, brow, boff, 0);
            gemm_blk(aloc, b2base, bl, e5, arow, aoff, brow, boff, 1);
            mbar_waitc(F1a, par);
            if (tid == 0) mbar_arm_tx(F1a, 16384);
            gemm_blk(pca, b2base, bp, e5, arow, aoff, brow, boff, 0);
            mbar_waitc(F1b, par);
            if (tid == 0) { mbar_arm_tx(F1b, 16384); mbar_arrive_remote(paC1); }
            gemm_blk(pca, b2base, bp, e5, arow, aoff, brow, boff, 1);

            // ---- epilogue2: clip e5; e3 *= e5 (f32 math, packed storage) ----
#pragma unroll
            for (int mt = 0; mt < 2; mt++)
#pragma unroll
                for (int half = 0; half < 2; half++)
#pragma unroll
                    for (int nt = 0; nt < 4; nt++) {
                        int j = mt * 16 + nt * 4 + half * 2;
                        int j2 = mt * 8 + nt * 2 + half;
                        float v0 = fminf(fmaxf(e5[j], 0.f), 1.f);
                        float v1 = fminf(fmaxf(e5[j + 1], 0.f), 1.f);
                        e5[j] = v0; e5[j + 1] = v1;
                        uint32_t ep = e3p[j2];
                        float t0 = __bfloat162float(*(__nv_bfloat16*)&ep);
                        uint32_t hi = ep >> 16;
                        float t1 = __bfloat162float(*(__nv_bfloat16*)&hi);
                        e3p[j2] = bf2(t0 * v0, t1 * v1);
                    }
            mbar_waitc(aC1, par);   // prev ca1-DMA delivered -> Aloc source free
            asm volatile("bar.sync %0, 128;" :: "r"(gbar) : "memory");  // WAR (group)
#pragma unroll
            for (int mt = 0; mt < 2; mt++)
#pragma unroll
                for (int half = 0; half < 2; half++) {
                    int row = mrow0 + 16 * mt + group + 8 * half;
#pragma unroll
                    for (int nt = 0; nt < 4; nt++) {
                        uint32_t p = e3p[mt * 8 + nt * 2 + half];
                        asm volatile("st.shared.b32 [%0], %1;"
                            :: "r"(aloc + tile_off(row, crel + 8 * nt + 2 * tid4)), "r"(p)
                            : "memory");
                    }
                }
            asm volatile("bar.sync %0, 128;" :: "r"(gbar) : "memory");  // RAW (group)
            __syncwarp();
            if (lane == 0) mbar_arrive_local(mSDme);
            if (tid == 0) {
                mbar_waitc(mSD0, sph0); sph0 ^= 1;
                FENCE_ASYNC();
                bulk_to_peer(pPE3, aloc, 16384, pF2a);
                mbar_waitc(mSD1, sph1); sph1 ^= 1;
                bulk_to_peer(pPE3 + 16384, aloc + 16384, 16384, pF2b);
            }
        } else {
            // ---- final step: ca1_99 -> out = ca1 @ Waction ----
#pragma unroll
            for (int nt = 0; nt < 4; nt++) {
                float4 bb = *(const float4*)(&g_basal2[i * 256 + colq + 8 * nt + 2 * tid4]);
#pragma unroll
                for (int mt = 0; mt < 2; mt++)
#pragma unroll
                    for (int half = 0; half < 2; half++) {
                        int j = mt * 16 + nt * 4 + half * 2;
                        d[j]     = fmaxf(fmaf(bb.x, fast_tanh(0.5f * d[j]),     bb.y), 0.f);
                        d[j + 1] = fmaxf(fmaf(bb.z, fast_tanh(0.5f * d[j + 1]), bb.w), 0.f);
                    }
            }
            float* red1 = (float*)(smem + SM_B2);   // B2 dead: [128][2][16]
            float* red2 = (float*)(smem + SM_PCA);  // peerCA1 dead in final step
            __syncthreads();                        // all warps past B2/PCA reads
            int ct = nq * 4 + tid4;
#pragma unroll
            for (int mt = 0; mt < 2; mt++)
#pragma unroll
                for (int half = 0; half < 2; half++) {
                    float p0 = 0.f, p1 = 0.f;
#pragma unroll
                    for (int nt = 0; nt < 4; nt++)
#pragma unroll
                        for (int c = 0; c < 2; c++) {
                            int cg = colq + 8 * nt + 2 * tid4 + c;
                            float v = d[mt * 16 + nt * 4 + half * 2 + c];
                            p0 = fmaf(v, Waction[cg * 2 + 0], p0);
                            p1 = fmaf(v, Waction[cg * 2 + 1], p1);
                        }
                    int row = mrow0 + 16 * mt + group + 8 * half;
                    red1[(row * 2 + 0) * 16 + ct] = p0;
                    red1[(row * 2 + 1) * 16 + ct] = p1;
                }
            __syncthreads();
            float s = 0.f;
            if (tid < 256) {
                int row = tid >> 1, a = tid & 1;
#pragma unroll
                for (int k = 0; k < 16; k++) s += red1[(row * 2 + a) * 16 + k];
                if (rank == 1) {
                    uint32_t r2;
                    asm("mapa.shared::cluster.u32 %0, %1, %2;"
                        : "=r"(r2) : "r"((uint32_t)(sbase + SM_PCA + (row * 2 + a) * 4)), "r"(0));
                    asm volatile("st.shared::cluster.b32 [%0], %1;" :: "r"(r2), "f"(s) : "memory");
                }
            }
            CSYNC();
            if (tid < 256 && rank == 0) {
                int row = tid >> 1, a = tid & 1;
                out[(size_t)(gbase + row) * 2 + a] = s + red2[row * 2 + a];
            }
            CSYNC();  // keep cluster alive until all remote traffic done
        }
    }
}

// ------------------------------ launch glue --------------------------------
extern "C" void kernel_launch(void* const* d_in, const int* in_sizes, int n_in,
                              void* d_out, int out_size) {
    const float* cue  = (const float*)d_in[0];
    const float* ec5i = (const float*)d_in[1];
    const float* W1   = (const float*)d_in[2];  // Wapical
    const float* Wb   = (const float*)d_in[3];  // Wbasal
    const float* W2   = (const float*)d_in[4];  // Wca1ec5
    const float* Wa   = (const float*)d_in[5];  // Waction
    const float* bias = (const float*)d_in[6];  // ca1bias
    float* out = (float*)d_out;

    prep_basal<<<100, 256>>>(Wb, bias);
    prep_w<<<512, 256>>>(W1, W2);
    prep_q0<<<1, 256>>>(W2);

    cudaFuncSetAttribute(rnn_main, cudaFuncAttributeMaxDynamicSharedMemorySize, SM_TOTAL);
    rnn_main<<<512, NTHR, SM_TOTAL>>>(cue, ec5i, Wa, out);
}

// round 16
// speedup vs baseline: 1.3998x; 1.1635x over previous
#include <cuda_runtime.h>
#include <cuda_bf16.h>
#include <cstdint>

#define T_STEPS 100

// ------------- device scratch (static; no allocations allowed) -------------
__device__ __align__(16) float2        g_basal2[T_STEPS * 256]; // {0.5*bm, 1.5*bm - bias}
__device__ __align__(16) float         g_q0[256];
__device__ __align__(16) __nv_bfloat16 g_W1T[256 * 256];        // [n][k] = Wapical[k][n]
__device__ __align__(16) __nv_bfloat16 g_W2T[256 * 256];        // [n][k] = Wca1ec5[k][n]

// ------------------------------ helpers ------------------------------------
__device__ __forceinline__ uint32_t smem_u32(const void* p) {
    uint32_t a;
    asm("{ .reg .u64 t; cvta.to.shared.u64 t, %1; cvt.u32.u64 %0, t; }" : "=r"(a) : "l"(p));
    return a;
}
__device__ __forceinline__ float fast_tanh(float x) {
    float y; asm("tanh.approx.f32 %0, %1;" : "=f"(y) : "f"(x)); return y;
}
__device__ __forceinline__ uint32_t bf2(float lo, float hi) {
    uint32_t r;
    asm("cvt.rn.bf16x2.f32 %0, %1, %2;" : "=r"(r) : "f"(hi), "f"(lo));
    return r;
}
#define CSYNC() do { \
    asm volatile("barrier.cluster.arrive.aligned;" ::: "memory"); \
    asm volatile("barrier.cluster.wait.aligned;" ::: "memory"); } while (0)

#define MBAR_INIT(addr, cnt) \
    asm volatile("mbarrier.init.shared.b64 [%0], %1;" :: "r"(addr), "r"((uint32_t)(cnt)) : "memory")

__device__ __forceinline__ void mbar_arrive_local(uint32_t a) {
    asm volatile("mbarrier.arrive.shared.b64 _, [%0];" :: "r"(a) : "memory");
}
__device__ __forceinline__ void mbar_arrive_remote(uint32_t a) {
    asm volatile("mbarrier.arrive.release.cluster.shared::cluster.b64 _, [%0];"
                 :: "r"(a) : "memory");
}
__device__ __forceinline__ void mbar_arm_tx(uint32_t a, uint32_t bytes) {
    asm volatile("mbarrier.arrive.expect_tx.shared.b64 _, [%0], %1;"
                 :: "r"(a), "r"(bytes) : "memory");
}
__device__ __forceinline__ void mbar_waitc(uint32_t mbar, uint32_t parity) {
    asm volatile(
        "{\n\t.reg .pred P;\n\t"
        "WL%=:\n\t"
        "mbarrier.try_wait.parity.acquire.cluster.shared::cta.b64 P, [%0], %1, 0x989680;\n\t"
        "@P bra.uni WD%=;\n\t"
        "bra.uni WL%=;\n\t"
        "WD%=:\n\t}"
        :: "r"(mbar), "r"(parity) : "memory");
}
// DSMEM DMA: local smem -> peer smem, completes on peer's mbarrier (tx bytes)
__device__ __forceinline__ void bulk_to_peer(uint32_t dst, uint32_t src, uint32_t bytes,
                                             uint32_t peer_mbar) {
    asm volatile(
        "cp.async.bulk.shared::cluster.shared::cta.mbarrier::complete_tx::bytes "
        "[%0], [%1], %2, [%3];"
        :: "r"(dst), "r"(src), "r"(bytes), "r"(peer_mbar) : "memory");
}
#define FENCE_ASYNC() asm volatile("fence.proxy.async.shared::cta;" ::: "memory")

#define LDSM4(R, addr) \
    asm volatile("ldmatrix.sync.aligned.m8n8.x4.shared.b16 {%0,%1,%2,%3}, [%4];" \
        : "=r"((R)[0]), "=r"((R)[1]), "=r"((R)[2]), "=r"((R)[3]) : "r"(addr))

#define MMA16816(D, A0, A1, A2, A3, B0, B1) \
    asm volatile("mma.sync.aligned.m16n8k16.row.col.f32.bf16.bf16.f32 " \
        "{%0,%1,%2,%3}, {%4,%5,%6,%7}, {%8,%9}, {%0,%1,%2,%3};" \
        : "+f"((D)[0]), "+f"((D)[1]), "+f"((D)[2]), "+f"((D)[3]) \
        : "r"(A0), "r"(A1), "r"(A2), "r"(A3), "r"(B0), "r"(B1))

// SW128 blocked layout. 32KB regions: [128 rows x 128 cols], 2 x 64-col blocks;
// 64KB B tiles: [128 rows x 256 cols], 4 blocks. col is region-relative.
__device__ __forceinline__ uint32_t tile_off(int row, int col) {
    uint32_t b = (uint32_t)((((row >> 3) + (col >> 6) * 16) << 10) +
                            ((row & 7) << 7) + ((col & 63) << 1));
    return b ^ ((b >> 3) & 0x70);
}

// ------------------------------ prep kernels -------------------------------
__global__ void prep_basal(const float* __restrict__ Wb, const float* __restrict__ bias) {
    __shared__ float ca3[256];
    int t = blockIdx.x, c = threadIdx.x;
    float x = (float)(t + 1);
    float d = x - (float)c * (100.0f / 255.0f);
    ca3[c] = expf(-d * d * (1.0f / 50.0f));
    __syncthreads();
    float s = 0.f;
    for (int j = 0; j < 256; j++) s = fmaf(ca3[j], Wb[j * 256 + c], s);
    g_basal2[t * 256 + c] = make_float2(0.5f * s, fmaf(1.5f, s, -bias[c]));
}

__global__ void prep_w(const float* __restrict__ W1, const float* __restrict__ W2) {
    int n = blockIdx.x & 255, k = threadIdx.x;
    if (blockIdx.x < 256) g_W1T[n * 256 + k] = __float2bfloat16(W1[k * 256 + n]);
    else                  g_W2T[n * 256 + k] = __float2bfloat16(W2[k * 256 + n]);
}

__global__ void prep_q0(const float* __restrict__ W2) {
    __shared__ float ca10[256];
    int e = threadIdx.x;
    ca10[e] = fmaxf(g_basal2[e].y, 0.f);
    __syncthreads();
    float s = 0.f;
    for (int c = 0; c < 256; c++) s = fmaf(ca10[c], W2[c * 256 + e], s);
    g_q0[e] = s;
}

// ------------------------------- main kernel -------------------------------
// SMEM: mbars @0; Aloc @1024 (32KB, own cols: ca1/e3 alternate);
// peerE3 @33792 (32KB, DMA dest); peerCA1 @66560 (32KB, DMA dest);
// B1 @99328 (64KB); B2 @164864 (64KB). Total 230400 <= 227KB max dynamic.
#define SM_MB    0
#define SM_ALOC  1024
#define SM_PE3   33792
#define SM_PCA   66560
#define SM_B1    99328
#define SM_B2    164864
#define SM_TOTAL 230400
#define NTHR     512

// one 64-col K block (4 kt): warp tile m32 x n32; A from a 32KB region
// (region-relative block kb in {0,1}), B cols at global K = bcol0 + kb*64 + ...
__device__ __forceinline__ void gemm_blk(uint32_t a_region, uint32_t b_base, int bcol0,
                                         float* acc, int arow, int aoff,
                                         int brow, int boff, int kb) {
#pragma unroll
    for (int q = 0; q < 4; q++) {
        const int ac = kb * 64 + q * 16;
        const int bc = bcol0 + kb * 64 + q * 16;
        uint32_t a0[4], a1[4], b[2][4];
        LDSM4(a0, a_region + tile_off(arow, ac + aoff));
        LDSM4(a1, a_region + tile_off(arow + 16, ac + aoff));
        LDSM4(b[0], b_base + tile_off(brow, bc + boff));
        LDSM4(b[1], b_base + tile_off(brow + 16, bc + boff));
#pragma unroll
        for (int nt = 0; nt < 4; nt++) {
            MMA16816(&acc[nt * 4], a0[0], a0[1], a0[2], a0[3],
                     b[nt >> 1][(nt & 1) * 2], b[nt >> 1][(nt & 1) * 2 + 1]);
            MMA16816(&acc[16 + nt * 4], a1[0], a1[1], a1[2], a1[3],
                     b[nt >> 1][(nt & 1) * 2], b[nt >> 1][(nt & 1) * 2 + 1]);
        }
    }
}

__global__ void __launch_bounds__(NTHR, 1) __cluster_dims__(2, 1, 1)
rnn_main(const float* __restrict__ cue, const float* __restrict__ ec5i,
         const float* __restrict__ Waction, float* __restrict__ out) {
    extern __shared__ char smem[];
    const uint32_t sbase = smem_u32(smem);
    const int tid = threadIdx.x, lane = tid & 31, wid = tid >> 5;
    const int mq = wid >> 2;                 // M quarter 0..3 (32 rows)
    const int nq = wid & 3;                  // N quarter 0..3 (32 cols)
    const int group = lane >> 2, tid4 = lane & 3;
    const int rank = blockIdx.x & 1;
    const int prk = rank ^ 1;
    const int gbase = (blockIdx.x >> 1) * 128;
    const int mrow0 = 32 * mq;
    const int colq = rank * 128 + 32 * nq;   // GLOBAL col base (gmem/basal indexing)
    const int crel = 32 * nq;                // region-relative col base
    const int arow = mrow0 + (lane & 15), aoff = (lane >> 4) * 8;
    const int brow = 32 * nq + ((lane >> 4) << 3) + (lane & 7);
    const int boff = ((lane >> 3) & 1) << 3;
    const int bl = rank * 128, bp = prk * 128;   // B col offsets: local/peer K half
    const bool gleader = (nq == 0 && lane == 0);
    const int gbar = 1 + mq;

    const uint32_t aloc = sbase + SM_ALOC;
    const uint32_t pe3  = sbase + SM_PE3;
    const uint32_t pca  = sbase + SM_PCA;
    const uint32_t b1base = sbase + SM_B1, b2base = sbase + SM_B2;
    const uint32_t F1 = sbase + SM_MB, F2 = F1 + 8, aE3 = F1 + 16, aC1 = F1 + 24;
    uint32_t pPE3, pPCA, pF1, pF2, paE3, paC1;
    asm("mapa.shared::cluster.u32 %0, %1, %2;" : "=r"(pPE3) : "r"(pe3), "r"(prk));
    asm("mapa.shared::cluster.u32 %0, %1, %2;" : "=r"(pPCA) : "r"(pca), "r"(prk));
    asm("mapa.shared::cluster.u32 %0, %1, %2;" : "=r"(pF1)  : "r"(F1),  "r"(prk));
    asm("mapa.shared::cluster.u32 %0, %1, %2;" : "=r"(pF2)  : "r"(F2),  "r"(prk));
    asm("mapa.shared::cluster.u32 %0, %1, %2;" : "=r"(paE3) : "r"(aE3), "r"(prk));
    asm("mapa.shared::cluster.u32 %0, %1, %2;" : "=r"(paC1) : "r"(aC1), "r"(prk));

    if (tid == 0) {
        MBAR_INIT(F1, 1); MBAR_INIT(F2, 1);
        MBAR_INIT(aE3, 1); MBAR_INIT(aC1, 1);
    }

    // ---- init: Aloc = cue own cols, peerE3 = cue peer cols (both local writes) ----
    {
        const float4* src = (const float4*)(cue + (size_t)gbase * 256);
        for (int idx = tid; idx < 8192; idx += NTHR) {
            int r = idx >> 6, c4 = (idx & 63) * 4;       // global col c4..c4+3
            float4 v = src[idx];
            uint32_t p0 = bf2(v.x, v.y), p1 = bf2(v.z, v.w);
            uint32_t reg = ((c4 >> 7) == rank) ? aloc : pe3;
            asm volatile("st.shared.v2.b32 [%0], {%1,%2};"
                         :: "r"(reg + tile_off(r, c4 & 127)), "r"(p0), "r"(p1) : "memory");
        }
    }
    // ---- resident weights (this CTA's 128-row N-half of W1T/W2T) ----
    {
        const uint4* w1 = (const uint4*)(g_W1T + (size_t)rank * 128 * 256);
        const uint4* w2 = (const uint4*)(g_W2T + (size_t)rank * 128 * 256);
        for (int idx = tid; idx < 4096; idx += NTHR) {
            int r = idx >> 5, c8 = (idx & 31) * 8;
            *(uint4*)(smem + SM_B1 + tile_off(r, c8)) = w1[idx];
            *(uint4*)(smem + SM_B2 + tile_off(r, c8)) = w2[idx];
        }
    }

    // ---- per-thread state: e5 = clip(ec5i + q0) f32; e3p = cue packed bf16 ----
    float e5[32], d[32];
    uint32_t e3p[16];
#pragma unroll
    for (int mt = 0; mt < 2; mt++)
#pragma unroll
        for (int half = 0; half < 2; half++) {
            int row = gbase + mrow0 + 16 * mt + group + 8 * half;
#pragma unroll
            for (int nt = 0; nt < 4; nt++) {
                int cg = colq + 8 * nt + 2 * tid4;
                int j = mt * 16 + nt * 4 + half * 2;
                float2 v5 = *(const float2*)(ec5i + (size_t)row * 256 + cg);
                float2 q  = *(const float2*)(g_q0 + cg);
                e5[j]     = fminf(fmaxf(v5.x + q.x, 0.f), 1.f);
                e5[j + 1] = fminf(fmaxf(v5.y + q.y, 0.f), 1.f);
                float2 v3 = *(const float2*)(cue + (size_t)row * 256 + cg);
                e3p[mt * 8 + nt * 2 + half] = bf2(v3.x, v3.y);
            }
        }
    __syncthreads();
    if (tid == 0) {
        mbar_arrive_local(F2);        // F2 phase0: peerE3 pre-filled with cue
        mbar_arm_tx(F1, 32768);       // F1 phase0: step-1 ca1 chunk DMAs
    }
    CSYNC();  // mbars + arms + tiles visible cluster-wide

    // this group's two 4KB chunks (rows 32mq..+31) inside the two 64-col blocks
    const uint32_t chk0 = (uint32_t)((0 * 16 + 4 * mq) * 1024);
    const uint32_t chk1 = (uint32_t)((1 * 16 + 4 * mq) * 1024);

    for (int i = 1; i < T_STEPS; i++) {
        const uint32_t par = (uint32_t)(i - 1) & 1u;

        // ---- GEMM1: S = ec3 @ W1 (Aloc halves, then wait F2, peerE3 halves) ----
#pragma unroll
        for (int j = 0; j < 32; j++) d[j] = 0.f;
        gemm_blk(aloc, b1base, bl, d, arow, aoff, brow, boff, 0);
        gemm_blk(aloc, b1base, bl, d, arow, aoff, brow, boff, 1);
        mbar_waitc(F2, par);
        if (tid == 0) { mbar_arm_tx(F2, 32768); mbar_arrive_remote(paE3); }
        gemm_blk(pe3, b1base, bp, d, arow, aoff, brow, boff, 0);
        gemm_blk(pe3, b1base, bp, d, arow, aoff, brow, boff, 1);

        if (i < T_STEPS - 1) {
            // ---- epilogue1: ca1 = relu(fma(0.5bm, tanh(S/2), 1.5bm-bias)) ----
#pragma unroll
            for (int nt = 0; nt < 4; nt++) {
                float4 bb = *(const float4*)(&g_basal2[i * 256 + colq + 8 * nt + 2 * tid4]);
#pragma unroll
                for (int mt = 0; mt < 2; mt++)
#pragma unroll
                    for (int half = 0; half < 2; half++) {
                        int j = mt * 16 + nt * 4 + half * 2;
                        d[j]     = fmaxf(fmaf(bb.x, fast_tanh(0.5f * d[j]),     bb.y), 0.f);
                        d[j + 1] = fmaxf(fmaf(bb.z, fast_tanh(0.5f * d[j + 1]), bb.w), 0.f);
                    }
            }
            mbar_waitc(aE3, par);   // prev e3-DMA fully delivered -> Aloc source free
            asm volatile("bar.sync %0, 128;" :: "r"(gbar) : "memory");  // WAR (group)
#pragma unroll
            for (int mt = 0; mt < 2; mt++)
#pragma unroll
                for (int half = 0; half < 2; half++) {
                    int row = mrow0 + 16 * mt + group + 8 * half;
#pragma unroll
                    for (int nt = 0; nt < 4; nt++) {
                        int j = mt * 16 + nt * 4 + half * 2;
                        uint32_t p = bf2(d[j], d[j + 1]);
                        asm volatile("st.shared.b32 [%0], %1;"
                            :: "r"(aloc + tile_off(row, crel + 8 * nt + 2 * tid4)), "r"(p)
                            : "memory");
                    }
                }
            asm volatile("bar.sync %0, 128;" :: "r"(gbar) : "memory");  // RAW (group)
            if (gleader) {          // ship this group's rows immediately
                FENCE_ASYNC();
                bulk_to_peer(pPCA + chk0, aloc + chk0, 4096, pF1);
                bulk_to_peer(pPCA + chk1, aloc + chk1, 4096, pF1);
            }

            // ---- GEMM2: e5 += ca1 @ W2 ----
            gemm_blk(aloc, b2base, bl, e5, arow, aoff, brow, boff, 0);
            gemm_blk(aloc, b2base, bl, e5, arow, aoff, brow, boff, 1);
            mbar_waitc(F1, par);
            if (tid == 0) { mbar_arm_tx(F1, 32768); mbar_arrive_remote(paC1); }
            gemm_blk(pca, b2base, bp, e5, arow, aoff, brow, boff, 0);
            gemm_blk(pca, b2base, bp, e5, arow, aoff, brow, boff, 1);

            // ---- epilogue2: clip e5; e3 *= e5 (f32 math, packed storage) ----
#pragma unroll
            for (int mt = 0; mt < 2; mt++)
#pragma unroll
                for (int half = 0; half < 2; half++)
#pragma unroll
                    for (int nt = 0; nt < 4; nt++) {
                        int j = mt * 16 + nt * 4 + half * 2;
                        int j2 = mt * 8 + nt * 2 + half;
                        float v0 = fminf(fmaxf(e5[j], 0.f), 1.f);
                        float v1 = fminf(fmaxf(e5[j + 1], 0.f), 1.f);
                        e5[j] = v0; e5[j + 1] = v1;
                        uint32_t ep = e3p[j2];
                        float t0 = __bfloat162float(*(__nv_bfloat16*)&ep);
                        uint32_t hi = ep >> 16;
                        float t1 = __bfloat162float(*(__nv_bfloat16*)&hi);
                        e3p[j2] = bf2(t0 * v0, t1 * v1);
                    }
            mbar_waitc(aC1, par);   // prev ca1-DMA delivered -> Aloc source free
            asm volatile("bar.sync %0, 128;" :: "r"(gbar) : "memory");  // WAR (group)
#pragma unroll
            for (int mt = 0; mt < 2; mt++)
#pragma unroll
                for (int half = 0; half < 2; half++) {
                    int row = mrow0 + 16 * mt + group + 8 * half;
#pragma unroll
                    for (int nt = 0; nt < 4; nt++) {
                        uint32_t p = e3p[mt * 8 + nt * 2 + half];
                        asm volatile("st.shared.b32 [%0], %1;"
                            :: "r"(aloc + tile_off(row, crel + 8 * nt + 2 * tid4)), "r"(p)
                            : "memory");
                    }
                }
            asm volatile("bar.sync %0, 128;" :: "r"(gbar) : "memory");  // RAW (group)
            if (gleader) {
                FENCE_ASYNC();
                bulk_to_peer(pPE3 + chk0, aloc + chk0, 4096, pF2);
                bulk_to_peer(pPE3 + chk1, aloc + chk1, 4096, pF2);
            }
        } else {
            // ---- final step: ca1_99 -> out = ca1 @ Waction ----
#pragma unroll
            for (int nt = 0; nt < 4; nt++) {
                float4 bb = *(const float4*)(&g_basal2[i * 256 + colq + 8 * nt + 2 * tid4]);
#pragma unroll
                for (int mt = 0; mt < 2; mt++)
#pragma unroll
                    for (int half = 0; half < 2; half++) {
                        int j = mt * 16 + nt * 4 + half * 2;
                        d[j]     = fmaxf(fmaf(bb.x, fast_tanh(0.5f * d[j]),     bb.y), 0.f);
                        d[j + 1] = fmaxf(fmaf(bb.z, fast_tanh(0.5f * d[j + 1]), bb.w), 0.f);
                    }
            }
            float* red1 = (float*)(smem + SM_B2);   // B2 dead: [128][2][16]
            float* red2 = (float*)(smem + SM_PCA);  // peerCA1 dead in final step
            __syncthreads();                        // all warps past B2/PCA reads
            int ct = nq * 4 + tid4;
#pragma unroll
            for (int mt = 0; mt < 2; mt++)
#pragma unroll
                for (int half = 0; half < 2; half++) {
                    float p0 = 0.f, p1 = 0.f;
#pragma unroll
                    for (int nt = 0; nt < 4; nt++)
#pragma unroll
                        for (int c = 0; c < 2; c++) {
                            int cg = colq + 8 * nt + 2 * tid4 + c;
                            float v = d[mt * 16 + nt * 4 + half * 2 + c];
                            p0 = fmaf(v, Waction[cg * 2 + 0], p0);
                            p1 = fmaf(v, Waction[cg * 2 + 1], p1);
                        }
                    int row = mrow0 + 16 * mt + group + 8 * half;
                    red1[(row * 2 + 0) * 16 + ct] = p0;
                    red1[(row * 2 + 1) * 16 + ct] = p1;
                }
            __syncthreads();
            float s = 0.f;
            if (tid < 256) {
                int row = tid >> 1, a = tid & 1;
#pragma unroll
                for (int k = 0; k < 16; k++) s += red1[(row * 2 + a) * 16 + k];
                if (rank == 1) {
                    uint32_t r2;
                    asm("mapa.shared::cluster.u32 %0, %1, %2;"
                        : "=r"(r2) : "r"((uint32_t)(sbase + SM_PCA + (row * 2 + a) * 4)), "r"(0));
                    asm volatile("st.shared::cluster.b32 [%0], %1;" :: "r"(r2), "f"(s) : "memory");
                }
            }
            CSYNC();
            if (tid < 256 && rank == 0) {
                int row = tid >> 1, a = tid & 1;
                out[(size_t)(gbase + row) * 2 + a] = s + red2[row * 2 + a];
            }
            CSYNC();  // keep cluster alive until all remote traffic done
        }
    }
}

// ------------------------------ launch glue --------------------------------
extern "C" void kernel_launch(void* const* d_in, const int* in_sizes, int n_in,
                              void* d_out, int out_size) {
    const float* cue  = (const float*)d_in[0];
    const float* ec5i = (const float*)d_in[1];
    const float* W1   = (const float*)d_in[2];  // Wapical
    const float* Wb   = (const float*)d_in[3];  // Wbasal
    const float* W2   = (const float*)d_in[4];  // Wca1ec5
    const float* Wa   = (const float*)d_in[5];  // Waction
    const float* bias = (const float*)d_in[6];  // ca1bias
    float* out = (float*)d_out;

    prep_basal<<<100, 256>>>(Wb, bias);
    prep_w<<<512, 256>>>(W1, W2);
    prep_q0<<<1, 256>>>(W2);

    cudaFuncSetAttribute(rnn_main, cudaFuncAttributeMaxDynamicSharedMemorySize, SM_TOTAL);
    rnn_main<<<512, NTHR, SM_TOTAL>>>(cue, ec5i, Wa, out);
}